// round 10
// baseline (speedup 1.0000x reference)
#include <cuda_runtime.h>
#include <cooperative_groups.h>
#include <cstdint>

namespace cg = cooperative_groups;

#define VOCAB   50257
#define BATCH   512
#define SEQ     1024

#define THR     256
#define CTAS    1184                    // 8 * 148 -> exactly co-resident
#define NTOK    (BATCH * SEQ)           // 524288
#define TOTAL_VEC ((BATCH * (size_t)VOCAB) / 4)   // exact: 6,432,896 float4

__device__ float g_inv_n[BATCH];

__global__ void __launch_bounds__(THR, 8)
tfidf_coop_kernel(const void* __restrict__ xraw,
                  const float* __restrict__ idf,
                  float* __restrict__ out)
{
    const int tid  = threadIdx.x;
    const int bid  = blockIdx.x;
    const int lane = tid & 31;
    const int wid  = tid >> 5;
    __shared__ float sh_part[THR / 32];

    // dtype detection, warp-local: if tokens are int32, a u64 read packs two
    // tokens and is >= VOCAB unless the odd one is 0; all-32-small has
    // probability (1/50257)^32 ~ 0. Uniform across all warps.
    const unsigned long long probe = ((const unsigned long long*)xraw)[lane];
    const int is64 = (__ballot_sync(0xffffffffu, probe >= (unsigned long long)VOCAB) == 0);

    // ---- Phase A1: first BATCH CTAs compute inv_n for their row ----
    if (bid < BATCH) {
        const size_t base = (size_t)bid * SEQ;
        float w = 0.0f;
        #pragma unroll
        for (int k = 0; k < SEQ / THR; ++k) {
            int tok;
            if (is64) tok = (int)((const long long*)xraw)[base + tid + k * THR];
            else      tok = ((const int*)xraw)[base + tid + k * THR];
            w += __ldg(&idf[tok]);
        }
        #pragma unroll
        for (int o = 16; o > 0; o >>= 1)
            w += __shfl_down_sync(0xffffffffu, w, o);
        if (lane == 0) sh_part[wid] = w;
        __syncthreads();
        if (wid == 0) {
            float v = (lane < THR / 32) ? sh_part[lane] : 0.0f;
            #pragma unroll
            for (int o = 4; o > 0; o >>= 1)
                v += __shfl_down_sync(0xffffffffu, v, o);
            if (lane == 0) g_inv_n[bid] = 1.0f / v;
        }
    }

    // ---- Phase A2: flat-interleaved zero of the whole output (fill shape) ----
    {
        const size_t stride = (size_t)CTAS * THR;
        const float4 z4 = make_float4(0.f, 0.f, 0.f, 0.f);
        #pragma unroll 4
        for (size_t i = (size_t)bid * THR + tid; i < TOTAL_VEC; i += stride)
            __stcs(&((float4*)out)[i], z4);
    }

    // ---- grid-wide barrier: zeros + inv_n visible everywhere ----
    cg::this_grid().sync();

    // ---- Phase B: flat scatter-accumulate (duplicates sum via RED) ----
    {
        const size_t gsz  = (size_t)CTAS * THR;
        for (size_t i = (size_t)bid * THR + tid; i < NTOK; i += gsz) {
            const int b   = (int)(i >> 10);
            int tok;
            if (is64) tok = (int)((const long long*)xraw)[i];
            else      tok = ((const int*)xraw)[i];
            const float val = __ldg(&idf[tok]) * g_inv_n[b];
            atomicAdd(&out[(size_t)b * VOCAB + tok], val);
        }
    }
}

extern "C" void kernel_launch(void* const* d_in, const int* in_sizes, int n_in,
                              void* d_out, int out_size)
{
    const void*  x   = d_in[0];
    const float* idf = (const float*)d_in[1];
    float*       out = (float*)d_out;

    cudaLaunchConfig_t cfg = {};
    cfg.gridDim  = dim3(CTAS);
    cfg.blockDim = dim3(THR);
    cfg.dynamicSmemBytes = 0;
    cfg.stream = 0;
    cudaLaunchAttribute attr[1];
    attr[0].id = cudaLaunchAttributeCooperative;
    attr[0].val.cooperative = 1;
    cfg.attrs = attr;
    cfg.numAttrs = 1;
    cudaLaunchKernelEx(&cfg, tfidf_coop_kernel, (const void*)x, idf, out);
}

// round 11
// speedup vs baseline: 1.3148x; 1.3148x over previous
#include <cuda_runtime.h>
#include <cstdint>

#define VOCAB   50257
#define BATCH   512
#define SEQ     1024
#define THR     256
#define HALF0   25128            // first-half length (second half = 25129)

__global__ void __launch_bounds__(THR, 8) __cluster_dims__(2, 1, 1)
tfidf_kernel(const void* __restrict__ xraw,
             const float* __restrict__ idf,
             float* __restrict__ out)
{
    const int b    = blockIdx.x >> 1;       // row
    const int r    = blockIdx.x & 1;        // rank in cluster pair
    const int tid  = threadIdx.x;
    const int lane = tid & 31;
    const int wid  = tid >> 5;
    __shared__ float sh_part[THR / 32];
    __shared__ float sh_sum[2];             // [0]=half0 sum, [1]=half1 sum

    // dtype detection, warp-local: if tokens are int32, a u64 read packs two
    // tokens and is >= VOCAB unless the odd one is 0; all-32-small has
    // probability (1/50257)^32 ~ 0. Uniform across all warps.
    const unsigned long long probe = ((const unsigned long long*)xraw)[lane];
    const int is64 = (__ballot_sync(0xffffffffu, probe >= (unsigned long long)VOCAB) == 0);

    // ---- my 512 tokens of this row + idf gathers (LDGs in flight early) ----
    const size_t base = (size_t)b * SEQ + (r << 9);
    int tok0, tok1;
    if (is64) {
        tok0 = (int)((const long long*)xraw)[base + tid];
        tok1 = (int)((const long long*)xraw)[base + tid + THR];
    } else {
        tok0 = ((const int*)xraw)[base + tid];
        tok1 = ((const int*)xraw)[base + tid + THR];
    }
    const float idf0 = __ldg(&idf[tok0]);
    const float idf1 = __ldg(&idf[tok1]);

    // ---- zero my half of the row (stores drain under the reduction) ----
    float* __restrict__ orow = out + (size_t)b * VOCAB;
    {
        float* p = orow + (r ? HALF0 : 0);
        const int n = r ? (VOCAB - HALF0) : HALF0;
        const int pre   = (int)(((16u - ((unsigned)(uintptr_t)p & 15u)) & 15u) >> 2);
        float4* __restrict__ pv = (float4*)(p + pre);
        const int nvec  = (n - pre) >> 2;
        const int tail0 = pre + (nvec << 2);

        if (tid < pre) p[tid] = 0.0f;                      // <=3 scalars
        const float4 z4 = make_float4(0.f, 0.f, 0.f, 0.f);
        #pragma unroll 4
        for (int i = tid; i < nvec; i += THR) pv[i] = z4;
        if (tid < n - tail0) p[tail0 + tid] = 0.0f;        // <=3 scalars
    }

    // ---- half-row sum of idf[tok] ----
    float w = idf0 + idf1;
    #pragma unroll
    for (int o = 16; o > 0; o >>= 1)
        w += __shfl_down_sync(0xffffffffu, w, o);
    if (lane == 0) sh_part[wid] = w;
    __syncthreads();
    if (wid == 0) {
        float v = (lane < THR / 32) ? sh_part[lane] : 0.0f;
        #pragma unroll
        for (int o = 4; o > 0; o >>= 1)
            v += __shfl_down_sync(0xffffffffu, v, o);
        if (lane == 0) {
            sh_sum[r] = v;                                  // own slot, local
            // push my half-sum into the peer CTA's sh_sum[r]
            uint32_t local = (uint32_t)__cvta_generic_to_shared(&sh_sum[r]);
            uint32_t remote;
            asm volatile("mapa.shared::cluster.u32 %0, %1, %2;"
                         : "=r"(remote) : "r"(local), "r"(r ^ 1));
            asm volatile("st.shared::cluster.f32 [%0], %1;"
                         :: "r"(remote), "f"(v) : "memory");
        }
    }

    // ---- one cluster barrier: release/acquire at cluster scope ----
    // Orders both CTAs' zero stores and the DSMEM half-sum exchange before
    // the REDs below; also acts as the block barrier for sh_sum.
    asm volatile("barrier.cluster.arrive.aligned;" ::: "memory");
    asm volatile("barrier.cluster.wait.aligned;"   ::: "memory");

    // ---- scatter-accumulate my 512 tokens into the (zeroed) full row ----
    // Duplicate tokens sum to count*idf*inv_n automatically; RED = no-return.
    const float inv_n = 1.0f / (sh_sum[0] + sh_sum[1]);
    atomicAdd(&orow[tok0], idf0 * inv_n);
    atomicAdd(&orow[tok1], idf1 * inv_n);
}

extern "C" void kernel_launch(void* const* d_in, const int* in_sizes, int n_in,
                              void* d_out, int out_size)
{
    const void*  x   = d_in[0];
    const float* idf = (const float*)d_in[1];
    float*       out = (float*)d_out;

    tfidf_kernel<<<BATCH * 2, THR>>>(x, idf, out);
}